// round 6
// baseline (speedup 1.0000x reference)
#include <cuda_runtime.h>
#include <cuda_bf16.h>
#include <math.h>

// ---------------- problem constants ----------------
#define Bsz 2
#define Sq  256
#define Dm  1024
#define Hh  8
#define HDm 128
#define Ll  16
#define FFd 2048
#define Vv  50257
#define SB  (Sq*Bsz)       // 512 rows, row r = s*Bsz + b  ([S,B,*] layout)
#define SBD (SB*Dm)        // 524288
#define ATT_SCALE 0.08838834764831843f

// ---------------- device scratch (static allocations only) -----------------
__device__ float g_x[SBD];            // current x  [S,B,D]
__device__ float g_q[SBD];            // q proj
__device__ float g_k[Ll*SBD];         // k proj per source
__device__ float g_v[Ll*SBD];         // v proj per source
__device__ float g_scores[Ll*16*Sq*Sq]; // [j][bh][q][k]
__device__ float g_comb[SBD];         // attention combine
__device__ float g_res[SBD];          // residual sum pre-LN
__device__ float g_sp[SBD];           // spikes
__device__ float g_h[SB*FFd];         // ff hidden / snn current (reused)
__device__ float g_lo[Ll*SBD];        // layer outputs

// ---------------- helpers ----------------
__device__ __forceinline__ float4 ldg4_guard(const float* p, int col, int N)
{
    float4 r;
    // vector load only if in-bounds AND 16B-aligned (Vv=50257 is odd!)
    if (col + 3 < N && ((((size_t)p) & 15) == 0)) {
        r = *(const float4*)(p);
    } else {
        r.x = (col+0<N)? p[0]:0.f; r.y = (col+1<N)? p[1]:0.f;
        r.z = (col+2<N)? p[2]:0.f; r.w = (col+3<N)? p[3]:0.f;
    }
    return r;
}

#define MMA16(buf) \
  _Pragma("unroll") \
  for (int kk=0;kk<16;kk++){ \
    float a0=As[buf][(ty<<2)+0][kk], a1=As[buf][(ty<<2)+1][kk], \
          a2=As[buf][(ty<<2)+2][kk], a3=As[buf][(ty<<2)+3][kk]; \
    float4 b4 = *(const float4*)&Bs[buf][kk][tx<<2]; \
    acc[0][0]=fmaf(a0,b4.x,acc[0][0]); acc[0][1]=fmaf(a0,b4.y,acc[0][1]); \
    acc[0][2]=fmaf(a0,b4.z,acc[0][2]); acc[0][3]=fmaf(a0,b4.w,acc[0][3]); \
    acc[1][0]=fmaf(a1,b4.x,acc[1][0]); acc[1][1]=fmaf(a1,b4.y,acc[1][1]); \
    acc[1][2]=fmaf(a1,b4.z,acc[1][2]); acc[1][3]=fmaf(a1,b4.w,acc[1][3]); \
    acc[2][0]=fmaf(a2,b4.x,acc[2][0]); acc[2][1]=fmaf(a2,b4.y,acc[2][1]); \
    acc[2][2]=fmaf(a2,b4.z,acc[2][2]); acc[2][3]=fmaf(a2,b4.w,acc[2][3]); \
    acc[3][0]=fmaf(a3,b4.x,acc[3][0]); acc[3][1]=fmaf(a3,b4.y,acc[3][1]); \
    acc[3][2]=fmaf(a3,b4.z,acc[3][2]); acc[3][3]=fmaf(a3,b4.w,acc[3][3]); \
  }

// ---------------- generic tiled SGEMM core: C[M,N] = A[M,K]@B[K,N] ----------
// A row-major lda=K (16B-aligned rows), B row-major ldb=N (any N).
// M multiple of 64, K multiple of 16. 256 threads, 64x64 tile, double buffered.
__device__ __forceinline__ void gemm_core(
    const float* __restrict__ A, const float* __restrict__ Bw,
    const float* __restrict__ bias, const float* __restrict__ res,
    float* __restrict__ C, int N, int K, int relu, int store_T)
{
    __shared__ __align__(16) float As[2][64][17];
    __shared__ __align__(16) float Bs[2][16][64];
    const int tid = threadIdx.x;
    const int tx = tid & 15, ty = tid >> 4;
    const int m0 = blockIdx.y << 6, n0 = blockIdx.x << 6;
    const int ar = tid >> 2, ac = (tid & 3) << 2;
    const int br = tid >> 4, bc = (tid & 15) << 2;
    float acc[4][4];
#pragma unroll
    for (int i=0;i<4;i++)
#pragma unroll
        for (int j=0;j<4;j++) acc[i][j]=0.f;

    const float* Ap = A + (size_t)(m0 + ar) * K + ac;
    const int nk = K >> 4;
    float4 aR, bR;

    // prologue kt = 0
    aR = *(const float4*)(Ap);
    bR = ldg4_guard(Bw + (size_t)br * N + n0 + bc, n0 + bc, N);
    As[0][ar][ac+0]=aR.x; As[0][ar][ac+1]=aR.y;
    As[0][ar][ac+2]=aR.z; As[0][ar][ac+3]=aR.w;
    *(float4*)&Bs[0][br][bc] = bR;
    __syncthreads();

    for (int kt = 1; kt < nk; kt++) {
        aR = *(const float4*)(Ap + kt*16);
        bR = ldg4_guard(Bw + (size_t)(kt*16 + br) * N + n0 + bc, n0 + bc, N);
        const int cb = (kt-1)&1, nb = kt&1;
        MMA16(cb);
        As[nb][ar][ac+0]=aR.x; As[nb][ar][ac+1]=aR.y;
        As[nb][ar][ac+2]=aR.z; As[nb][ar][ac+3]=aR.w;
        *(float4*)&Bs[nb][br][bc] = bR;
        __syncthreads();
    }
    { const int lb = (nk-1)&1; MMA16(lb); }

    // epilogue
#pragma unroll
    for (int i=0;i<4;i++){
        int m = m0 + (ty<<2) + i;
#pragma unroll
        for (int j=0;j<4;j++){
            int nn = n0 + (tx<<2) + j;
            if (nn >= N) continue;
            float v = acc[i][j];
            if (bias) v += bias[nn];
            if (res)  v += res[(size_t)m*N + nn];
            if (relu) v = fmaxf(v, 0.f);
            if (!store_T) {
                C[(size_t)m*N + nn] = v;
            } else {                      // logits: row (s*B+b) -> out[b][s][v]
                int s = m >> 1, b = m & 1;
                C[(size_t)(b*Sq + s)*N + nn] = v;
            }
        }
    }
}

__global__ void k_gemm(const float* __restrict__ A, const float* __restrict__ Bw,
                       const float* __restrict__ bias, const float* __restrict__ res,
                       float* __restrict__ C, int N, int K, int relu, int store_T)
{
    gemm_core(A, Bw, bias, res, C, N, K, relu, store_T);
}

// ---------------- batched Q/K/V projection: grid.z = 2n+1 ------------------
__global__ void k_kvq(const float* __restrict__ Wq, const float* __restrict__ bq,
                      const float* __restrict__ Wk, const float* __restrict__ bk,
                      const float* __restrict__ Wv, const float* __restrict__ bv,
                      int n)
{
    int z = blockIdx.z;
    const float *A, *W, *bi; float* C;
    if (z == 2*n) { A = g_x; W = Wq; bi = bq; C = g_q; }
    else {
        int isv = (z >= n) ? 1 : 0;
        int j = isv ? z - n : z;
        A = (j == 0) ? g_x : g_lo + (size_t)(j-1)*SBD;
        W = isv ? Wv : Wk;
        bi = isv ? bv : bk;
        C = (isv ? g_v : g_k) + (size_t)j*SBD;
    }
    gemm_core(A, W, bi, nullptr, C, Dm, Dm, 0, 0);
}

// ---------------- embedding + positional encoding ---------------------------
__global__ void k_embed(const int* __restrict__ src, const float* __restrict__ emb)
{
    int idx = blockIdx.x * 256 + threadIdx.x;       // over SBD
    int d = idx & (Dm-1);
    int r = idx >> 10;
    int b = r & 1, s = r >> 1;
    int tok = src[b*Sq + s];
    float v = emb[(size_t)tok*Dm + d] * 32.0f;      // sqrt(1024)
    int de = d & ~1;
    float ang = (float)s * expf((float)de * -0.008994473019508f); // -ln(1e4)/1024
    float pe = (d & 1) ? cosf(ang) : sinf(ang);
    g_x[idx] = v + pe;
}

// ---------------- scores: per (source j, head bh) NT-GEMM -------------------
#define MMA16S(buf) \
  _Pragma("unroll") \
  for (int kk=0;kk<16;kk++){ \
    float a0=Qs[buf][(ty<<2)+0][kk], a1=Qs[buf][(ty<<2)+1][kk], \
          a2=Qs[buf][(ty<<2)+2][kk], a3=Qs[buf][(ty<<2)+3][kk]; \
    float b0=Ks[buf][(tx<<2)+0][kk], b1=Ks[buf][(tx<<2)+1][kk], \
          b2=Ks[buf][(tx<<2)+2][kk], b3=Ks[buf][(tx<<2)+3][kk]; \
    acc[0][0]=fmaf(a0,b0,acc[0][0]); acc[0][1]=fmaf(a0,b1,acc[0][1]); \
    acc[0][2]=fmaf(a0,b2,acc[0][2]); acc[0][3]=fmaf(a0,b3,acc[0][3]); \
    acc[1][0]=fmaf(a1,b0,acc[1][0]); acc[1][1]=fmaf(a1,b1,acc[1][1]); \
    acc[1][2]=fmaf(a1,b2,acc[1][2]); acc[1][3]=fmaf(a1,b3,acc[1][3]); \
    acc[2][0]=fmaf(a2,b0,acc[2][0]); acc[2][1]=fmaf(a2,b1,acc[2][1]); \
    acc[2][2]=fmaf(a2,b2,acc[2][2]); acc[2][3]=fmaf(a2,b3,acc[2][3]); \
    acc[3][0]=fmaf(a3,b0,acc[3][0]); acc[3][1]=fmaf(a3,b1,acc[3][1]); \
    acc[3][2]=fmaf(a3,b2,acc[3][2]); acc[3][3]=fmaf(a3,b3,acc[3][3]); \
  }

__global__ void k_scores(int n)
{
    __shared__ float Qs[2][64][17];
    __shared__ float Ks[2][64][17];
    const int tid = threadIdx.x;
    const int tx = tid & 15, ty = tid >> 4;
    const int ar = tid >> 2, ac = (tid & 3) << 2;
    const int z = blockIdx.z;                 // z = j*16 + bh
    const int bh = z & 15;
    const int b = bh >> 3, h = bh & 7;
    const int LDX = Bsz * Dm;                 // 2048
    const float* Aq = g_q + b*Dm + h*HDm;
    const float* Bk = g_k + (size_t)(z >> 4)*SBD + b*Dm + h*HDm;
    float* C = g_scores + (size_t)z * Sq * Sq;
    const int m0 = blockIdx.y << 6, n0 = blockIdx.x << 6;
    float acc[4][4];
#pragma unroll
    for (int i=0;i<4;i++)
#pragma unroll
        for (int j=0;j<4;j++) acc[i][j]=0.f;

    float4 qR, kR;
    qR = *(const float4*)(Aq + (size_t)(m0+ar)*LDX + ac);
    kR = *(const float4*)(Bk + (size_t)(n0+ar)*LDX + ac);
    Qs[0][ar][ac+0]=qR.x; Qs[0][ar][ac+1]=qR.y; Qs[0][ar][ac+2]=qR.z; Qs[0][ar][ac+3]=qR.w;
    Ks[0][ar][ac+0]=kR.x; Ks[0][ar][ac+1]=kR.y; Ks[0][ar][ac+2]=kR.z; Ks[0][ar][ac+3]=kR.w;
    __syncthreads();

    for (int kt = 1; kt < 8; kt++) {          // HD=128 -> 8 k-tiles
        qR = *(const float4*)(Aq + (size_t)(m0+ar)*LDX + kt*16 + ac);
        kR = *(const float4*)(Bk + (size_t)(n0+ar)*LDX + kt*16 + ac);
        const int cb = (kt-1)&1, nb = kt&1;
        MMA16S(cb);
        Qs[nb][ar][ac+0]=qR.x; Qs[nb][ar][ac+1]=qR.y; Qs[nb][ar][ac+2]=qR.z; Qs[nb][ar][ac+3]=qR.w;
        Ks[nb][ar][ac+0]=kR.x; Ks[nb][ar][ac+1]=kR.y; Ks[nb][ar][ac+2]=kR.z; Ks[nb][ar][ac+3]=kR.w;
        __syncthreads();
    }
    MMA16S(1);

#pragma unroll
    for (int i=0;i<4;i++){
        int m = m0 + (ty<<2) + i;
#pragma unroll
        for (int j=0;j<4;j++){
            int nn = n0 + (tx<<2) + j;
            C[(size_t)m*Sq + nn] = acc[i][j] * ATT_SCALE;
        }
    }
}

// ---------------- softmax over keys x learned layer weight ------------------
__global__ void k_softmax(const float* __restrict__ lw, int n)
{
    int row  = blockIdx.x * 8 + (threadIdx.x >> 5);   // rows = n*16*256
    int lane = threadIdx.x & 31;
    float* p = g_scores + (size_t)row * Sq;
    float x[8];
#pragma unroll
    for (int i=0;i<8;i++) x[i] = p[lane + (i<<5)];
    float mx = x[0];
#pragma unroll
    for (int i=1;i<8;i++) mx = fmaxf(mx, x[i]);
#pragma unroll
    for (int off=16;off>0;off>>=1) mx = fmaxf(mx, __shfl_xor_sync(0xffffffffu, mx, off));
    float sum = 0.f;
#pragma unroll
    for (int i=0;i<8;i++){ x[i] = expf(x[i]-mx); sum += x[i]; }
#pragma unroll
    for (int off=16;off>0;off>>=1) sum += __shfl_xor_sync(0xffffffffu, sum, off);
    int j = row >> 12;                                 // row / (16*256)
    float lm = -1e30f;
    for (int jj=0;jj<n;jj++) lm = fmaxf(lm, lw[jj]);
    float ls = 0.f;
    for (int jj=0;jj<n;jj++) ls += expf(lw[jj]-lm);
    float wj = expf(lw[j]-lm) / ls;
    float sc = wj / sum;
#pragma unroll
    for (int i=0;i<8;i++) p[lane + (i<<5)] = x[i] * sc;
}

// ---------------- comb: per head, sum over sources j of attn_j @ v_j --------
__global__ void k_comb(int n)
{
    __shared__ __align__(16) float As[2][64][17];
    __shared__ __align__(16) float Bs[2][16][64];
    const int tid = threadIdx.x;
    const int tx = tid & 15, ty = tid >> 4;
    const int ar = tid >> 2, ac = (tid & 3) << 2;
    const int br = tid >> 4, bc = (tid & 15) << 2;
    const int bh = blockIdx.z, b = bh >> 3, h = bh & 7;
    const int m0 = blockIdx.y << 6, n0 = blockIdx.x << 6;   // q tile, d tile
    float acc[4][4];
#pragma unroll
    for (int i=0;i<4;i++)
#pragma unroll
        for (int j=0;j<4;j++) acc[i][j]=0.f;

    for (int j=0;j<n;j++){
        const float* Aj = g_scores + (size_t)(j*16 + bh) * Sq * Sq;   // [q][k] ld=256
        const float* Vj = g_v + (size_t)j*SBD + b*Dm + h*HDm;          // [k][d] ld=2048
        float4 aR = *(const float4*)(Aj + (size_t)(m0+ar)*Sq + ac);
        float4 bR = *(const float4*)(Vj + (size_t)br*2048 + n0 + bc);
        As[0][ar][ac+0]=aR.x; As[0][ar][ac+1]=aR.y; As[0][ar][ac+2]=aR.z; As[0][ar][ac+3]=aR.w;
        *(float4*)&Bs[0][br][bc] = bR;
        __syncthreads();
        for (int kt = 1; kt < 16; kt++) {     // Sq=256 -> 16 k-tiles
            aR = *(const float4*)(Aj + (size_t)(m0+ar)*Sq + kt*16 + ac);
            bR = *(const float4*)(Vj + (size_t)(kt*16+br)*2048 + n0 + bc);
            const int cb = (kt-1)&1, nb = kt&1;
            MMA16(cb);
            As[nb][ar][ac+0]=aR.x; As[nb][ar][ac+1]=aR.y; As[nb][ar][ac+2]=aR.z; As[nb][ar][ac+3]=aR.w;
            *(float4*)&Bs[nb][br][bc] = bR;
            __syncthreads();
        }
        MMA16(1);
        __syncthreads();
    }

#pragma unroll
    for (int i=0;i<4;i++){
        int q = m0 + (ty<<2) + i;
        int r = q*Bsz + b;
#pragma unroll
        for (int j=0;j<4;j++){
            int d = h*HDm + n0 + (tx<<2) + j;
            g_comb[(size_t)r*Dm + d] = acc[i][j];
        }
    }
}

// ---------------- layernorm over D of in, write out (and optional copy) -----
__global__ void k_ln(const float* __restrict__ in, const float* __restrict__ g,
                     const float* __restrict__ be, float* __restrict__ out,
                     float* __restrict__ out2)
{
    __shared__ float s1[8], s2[8];
    __shared__ float smean, srstd;
    int r = blockIdx.x, tid = threadIdx.x;
    int lane = tid & 31, wid = tid >> 5;
    const float* row = in + (size_t)r*Dm;
    float v[4], sum = 0.f, sq = 0.f;
#pragma unroll
    for (int i=0;i<4;i++){ v[i] = row[tid + (i<<8)]; sum += v[i]; sq += v[i]*v[i]; }
#pragma unroll
    for (int off=16;off>0;off>>=1){
        sum += __shfl_xor_sync(0xffffffffu, sum, off);
        sq  += __shfl_xor_sync(0xffffffffu, sq,  off);
    }
    if (lane == 0){ s1[wid] = sum; s2[wid] = sq; }
    __syncthreads();
    if (tid == 0){
        float a=0.f, c=0.f;
        for (int i=0;i<8;i++){ a += s1[i]; c += s2[i]; }
        float mean = a * (1.f/1024.f);
        float var  = c * (1.f/1024.f) - mean*mean;
        smean = mean; srstd = rsqrtf(var + 1e-5f);
    }
    __syncthreads();
    float mean = smean, rstd = srstd;
#pragma unroll
    for (int i=0;i<4;i++){
        int d = tid + (i<<8);
        float o = (v[i]-mean)*rstd*g[d] + be[d];
        out[(size_t)r*Dm + d] = o;
        if (out2) out2[(size_t)r*Dm + d] = o;
    }
}

// ---------------- SNN scan: one block per batch, 1024 threads ---------------
__global__ void k_snn(const float* __restrict__ cur, float* __restrict__ sp)
{
    __shared__ float red[32];
    __shared__ float redt;
    int b = blockIdx.x, d = threadIdx.x;
    int lane = d & 31, wid = d >> 5;
    float mem = 0.f, thr = 1.0f;
    float nxt = cur[(size_t)b*Dm + d];               // t = 0 row = (0*B+b)
    for (int t=0;t<Sq;t++){
        float cin = nxt;
        if (t+1 < Sq) nxt = cur[(size_t)((t+1)*Bsz + b)*Dm + d];
        float v = mem;
#pragma unroll
        for (int off=16;off>0;off>>=1) v += __shfl_xor_sync(0xffffffffu, v, off);
        if (lane == 0) red[wid] = v;
        __syncthreads();
        if (wid == 0){
            float u = red[lane];
#pragma unroll
            for (int off=16;off>0;off>>=1) u += __shfl_xor_sync(0xffffffffu, u, off);
            if (lane == 0) redt = u;
        }
        __syncthreads();
        float c = cin - 0.1f * redt;
        mem = 0.9f * mem + c;
        float s = (mem >= thr) ? 1.f : 0.f;
        mem -= s * thr;
        thr = 0.9f * thr + 0.1f * s;
        sp[(size_t)(t*Bsz + b)*Dm + d] = s;
    }
}

// ---------------- host orchestration ----------------------------------------
extern "C" void kernel_launch(void* const* d_in, const int* in_sizes, int n_in,
                              void* d_out, int out_size)
{
    const int*   src  = (const int*)  d_in[0];
    const float* emb  = (const float*)d_in[1];
    const float* Wq   = (const float*)d_in[2];
    const float* bq   = (const float*)d_in[3];
    const float* Wk   = (const float*)d_in[4];
    const float* bk   = (const float*)d_in[5];
    const float* Wv   = (const float*)d_in[6];
    const float* bv   = (const float*)d_in[7];
    const float* Wo   = (const float*)d_in[8];
    const float* bo   = (const float*)d_in[9];
    const float* layer_w = (const float*)d_in[10];
    const float* Wsnn = (const float*)d_in[11];
    const float* bsnn = (const float*)d_in[12];
    const float* W1   = (const float*)d_in[13];
    const float* b1   = (const float*)d_in[14];
    const float* W2   = (const float*)d_in[15];
    const float* b2   = (const float*)d_in[16];
    const float* g1   = (const float*)d_in[17];
    const float* be1  = (const float*)d_in[18];
    const float* g2   = (const float*)d_in[19];
    const float* be2  = (const float*)d_in[20];
    const float* Wout = (const float*)d_in[21];
    const float* bout = (const float*)d_in[22];
    float* out = (float*)d_out;

    float *px, *pcomb, *pres, *psp, *ph, *plo;
    cudaGetSymbolAddress((void**)&px,    g_x);
    cudaGetSymbolAddress((void**)&pcomb, g_comb);
    cudaGetSymbolAddress((void**)&pres,  g_res);
    cudaGetSymbolAddress((void**)&psp,   g_sp);
    cudaGetSymbolAddress((void**)&ph,    g_h);
    cudaGetSymbolAddress((void**)&plo,   g_lo);

    k_embed<<<SBD/256, 256>>>(src, emb);

    for (int l=0; l<Ll; l++){
        int n = l + 1;
        const float* Wql = Wq + (size_t)l*Dm*Dm;
        const float* Wkl = Wk + (size_t)l*Dm*Dm;
        const float* Wvl = Wv + (size_t)l*Dm*Dm;

        // Q + n*K + n*V projections, batched over grid.z
        k_kvq<<<dim3(16,8,2*n+1), 256>>>(Wql, bq + l*Dm, Wkl, bk + l*Dm,
                                         Wvl, bv + l*Dm, n);
        // attention scores, per (source, head)
        k_scores<<<dim3(4,4,n*16), 256>>>(n);
        // softmax over keys x layer-weight softmax
        k_softmax<<<n*16*Sq/8, 256>>>(layer_w + l*(Ll+1), n);
        // combine over (k, source)
        k_comb<<<dim3(2,4,16), 256>>>(n);
        // output projection + residual
        k_gemm<<<dim3(16,8), 256>>>(pcomb, Wo + (size_t)l*Dm*Dm, bo + l*Dm,
                                    px, pres, Dm, Dm, 0, 0);
        // LN1 -> new x
        k_ln<<<SB, 256>>>(pres, g1 + l*Dm, be1 + l*Dm, px, (float*)nullptr);
        // SNN input current
        k_gemm<<<dim3(16,8), 256>>>(px, Wsnn + (size_t)l*Dm*Dm, bsnn + l*Dm,
                                    (const float*)nullptr, ph, Dm, Dm, 0, 0);
        // membrane scan -> spikes
        k_snn<<<Bsz, 1024>>>(ph, psp);
        // FF1 (relu)
        k_gemm<<<dim3(32,8), 256>>>(psp, W1 + (size_t)l*Dm*FFd, b1 + l*FFd,
                                    (const float*)nullptr, ph, FFd, Dm, 1, 0);
        // FF2 + residual
        k_gemm<<<dim3(16,8), 256>>>(ph, W2 + (size_t)l*FFd*Dm, b2 + l*Dm,
                                    px, pres, Dm, FFd, 0, 0);
        // LN2 -> new x, also store as this layer's output
        k_ln<<<SB, 256>>>(pres, g2 + l*Dm, be2 + l*Dm, px, plo + (size_t)l*SBD);
    }

    // final logits with transposed store into [B,S,V]
    k_gemm<<<dim3((Vv+63)/64, 8), 256>>>(px, Wout, bout, (const float*)nullptr,
                                         out, Vv, Dm, 0, 1);
}